// round 7
// baseline (speedup 1.0000x reference)
#include <cuda_runtime.h>

#define N_NODES 100000
#define N_EDGES 800000
#define IN_DIM 128
#define HID_DIM 256
#define OUT_DIM 40

// ---------------- scratch (static __device__ arrays; no allocs) ----------------
__device__ float4 g_agg1[N_NODES * IN_DIM / 4];    // 51.2 MB  neighbor-sum of x
__device__ float4 g_h[N_NODES * HID_DIM / 4];      // 102.4 MB hidden activations
__device__ float4 g_pq[N_NODES * 2 * OUT_DIM / 4]; // 32 MB    [p = h@W2l | q = h@W2r]
__device__ float4 g_agg2[N_NODES * OUT_DIM / 4];   // 16 MB    neighbor-sum of p
__device__ float  g_inv[N_NODES];                  // 1/max(deg,1)
__device__ int    g_cnt[N_NODES];

// ---------------- zero scratch ----------------
__global__ void k_zero() {
    int i = blockIdx.x * blockDim.x + threadIdx.x;
    float4 z = make_float4(0.f, 0.f, 0.f, 0.f);
    if (i < N_NODES * IN_DIM / 4) g_agg1[i] = z;
    if (i < N_NODES * OUT_DIM / 4) g_agg2[i] = z;
    if (i < N_NODES) g_cnt[i] = 0;
}

// ---------------- edge pass 1: scatter-add x[src] -> agg1[dst], degree count ----------------
// edge_index is INT32 (JAX x64 disabled downcasts the requested int64).
__global__ void k_edge1(const float4* __restrict__ x4, const int* __restrict__ ei) {
    int idx = blockIdx.x * blockDim.x + threadIdx.x;
    if (idx >= N_EDGES * 32) return;
    int e = idx >> 5;
    int c = idx & 31;
    int s = __ldg(&ei[e]);
    int d = __ldg(&ei[N_EDGES + e]);
    float4 v = x4[(size_t)s * 32 + c];
    float* a = ((float*)g_agg1) + (size_t)d * IN_DIM + c * 4;
    atomicAdd(a + 0, v.x);
    atomicAdd(a + 1, v.y);
    atomicAdd(a + 2, v.z);
    atomicAdd(a + 3, v.w);
    if (c == 0) atomicAdd(&g_cnt[d], 1);
}

__global__ void k_inv() {
    int i = blockIdx.x * blockDim.x + threadIdx.x;
    if (i < N_NODES) g_inv[i] = 1.0f / fmaxf((float)g_cnt[i], 1.0f);
}

// ---------------- GEMM1: h = relu((agg1*inv) @ W1l + x @ W1r + b1) ----------------
// BM=64, BN=64, BK=16, 256 threads (16x16), 4x4 per thread.
#define AS_STRIDE 68  // padded, multiple of 4 floats -> 16B-aligned rows
__global__ __launch_bounds__(256) void k_gemm1(const float4* __restrict__ x4,
                                               const float4* __restrict__ W1l4,
                                               const float4* __restrict__ W1r4,
                                               const float4* __restrict__ b14) {
    __shared__ __align__(16) float As[16 * AS_STRIDE];
    __shared__ __align__(16) float Bs[16 * 64];

    int tid = threadIdx.x;
    int tx = tid & 15;          // output col group
    int ty = tid >> 4;          // output row group
    int rowBase = blockIdx.y * 64;
    int colBlk = blockIdx.x;    // 0..3 (64 cols each)

    int lm = tid >> 2;          // 0..63 row within tile (A load)
    int lc4 = tid & 3;          // 0..3 float4 within 16-wide k chunk
    int arow = rowBase + lm;
    bool arow_ok = arow < N_NODES;
    float sc = arow_ok ? g_inv[arow] : 0.f;

    int bk = tid >> 4;          // 0..15 k row (B load)
    int bc4 = tid & 15;         // 0..15 float4 col

    float acc[4][4];
#pragma unroll
    for (int i = 0; i < 4; i++)
#pragma unroll
        for (int j = 0; j < 4; j++) acc[i][j] = 0.f;

#pragma unroll
    for (int phase = 0; phase < 2; ++phase) {
        const float4* A4 = phase ? x4 : g_agg1;
        const float4* W4 = phase ? W1r4 : W1l4;
        for (int kt = 0; kt < IN_DIM; kt += 16) {
            // load A tile (transposed into As[k][m]) with inv-scaling on phase 0
            float4 v = make_float4(0.f, 0.f, 0.f, 0.f);
            if (arow_ok) {
                v = A4[(size_t)arow * 32 + (kt >> 2) + lc4];
                if (phase == 0) { v.x *= sc; v.y *= sc; v.z *= sc; v.w *= sc; }
            }
            As[(lc4 * 4 + 0) * AS_STRIDE + lm] = v.x;
            As[(lc4 * 4 + 1) * AS_STRIDE + lm] = v.y;
            As[(lc4 * 4 + 2) * AS_STRIDE + lm] = v.z;
            As[(lc4 * 4 + 3) * AS_STRIDE + lm] = v.w;
            // load B tile: Bs[k][c] = W[(kt+k)*256 + colBlk*64 + c]
            float4 w = W4[(size_t)(kt + bk) * 64 + colBlk * 16 + bc4];
            *(float4*)&Bs[bk * 64 + bc4 * 4] = w;
            __syncthreads();
#pragma unroll
            for (int k = 0; k < 16; ++k) {
                float4 a = *(const float4*)&As[k * AS_STRIDE + ty * 4];
                float4 b = *(const float4*)&Bs[k * 64 + tx * 4];
                float av[4] = {a.x, a.y, a.z, a.w};
                float bv[4] = {b.x, b.y, b.z, b.w};
#pragma unroll
                for (int i = 0; i < 4; i++)
#pragma unroll
                    for (int j = 0; j < 4; j++) acc[i][j] += av[i] * bv[j];
            }
            __syncthreads();
        }
    }

    float4 bb = b14[colBlk * 16 + tx];
    float bv[4] = {bb.x, bb.y, bb.z, bb.w};
#pragma unroll
    for (int i = 0; i < 4; i++) {
        int row = rowBase + ty * 4 + i;
        if (row < N_NODES) {
            float4 o;
            o.x = fmaxf(acc[i][0] + bv[0], 0.f);
            o.y = fmaxf(acc[i][1] + bv[1], 0.f);
            o.z = fmaxf(acc[i][2] + bv[2], 0.f);
            o.w = fmaxf(acc[i][3] + bv[3], 0.f);
            g_h[(size_t)row * 64 + colBlk * 16 + tx] = o;
        }
    }
}

// ---------------- GEMM2: pq = h @ [W2l | W2r]  (N x 80, K=256) ----------------
// BM=64, BN=80, BK=16, 320 threads (20x16), 4x4 per thread.
__global__ __launch_bounds__(320) void k_gemm2(const float4* __restrict__ W2l4,
                                               const float4* __restrict__ W2r4) {
    __shared__ __align__(16) float As[16 * AS_STRIDE];
    __shared__ __align__(16) float Bs[16 * 80];

    int tid = threadIdx.x;
    int tx = tid % 20;
    int ty = tid / 20;
    int rowBase = blockIdx.y * 64;

    float acc[4][4];
#pragma unroll
    for (int i = 0; i < 4; i++)
#pragma unroll
        for (int j = 0; j < 4; j++) acc[i][j] = 0.f;

    int lm = tid >> 2;   // A loader: only tid<256 used -> lm 0..63
    int lc4 = tid & 3;
    int arow = rowBase + lm;
    bool aload = (tid < 256) && (arow < N_NODES);

    int bk = tid / 20;   // 0..15
    int bc4 = tid % 20;  // 0..19

    for (int kt = 0; kt < HID_DIM; kt += 16) {
        if (tid < 256) {
            float4 v = make_float4(0.f, 0.f, 0.f, 0.f);
            if (aload) v = g_h[(size_t)arow * 64 + (kt >> 2) + lc4];
            As[(lc4 * 4 + 0) * AS_STRIDE + lm] = v.x;
            As[(lc4 * 4 + 1) * AS_STRIDE + lm] = v.y;
            As[(lc4 * 4 + 2) * AS_STRIDE + lm] = v.z;
            As[(lc4 * 4 + 3) * AS_STRIDE + lm] = v.w;
        }
        float4 w;
        if (bc4 < 10) w = W2l4[(size_t)(kt + bk) * 10 + bc4];
        else          w = W2r4[(size_t)(kt + bk) * 10 + (bc4 - 10)];
        *(float4*)&Bs[bk * 80 + bc4 * 4] = w;
        __syncthreads();
#pragma unroll
        for (int k = 0; k < 16; ++k) {
            float4 a = *(const float4*)&As[k * AS_STRIDE + ty * 4];
            float4 b = *(const float4*)&Bs[k * 80 + tx * 4];
            float av[4] = {a.x, a.y, a.z, a.w};
            float bv[4] = {b.x, b.y, b.z, b.w};
#pragma unroll
            for (int i = 0; i < 4; i++)
#pragma unroll
                for (int j = 0; j < 4; j++) acc[i][j] += av[i] * bv[j];
        }
        __syncthreads();
    }

#pragma unroll
    for (int i = 0; i < 4; i++) {
        int row = rowBase + ty * 4 + i;
        if (row < N_NODES) {
            g_pq[(size_t)row * 20 + tx] =
                make_float4(acc[i][0], acc[i][1], acc[i][2], acc[i][3]);
        }
    }
}

// ---------------- edge pass 2: scatter-add p[src] -> agg2[dst] (40 floats) ----------------
__global__ void k_scatter2(const int* __restrict__ ei) {
    int idx = blockIdx.x * blockDim.x + threadIdx.x;
    if (idx >= N_EDGES * 10) return;
    int e = idx / 10;
    int c = idx % 10;
    int s = __ldg(&ei[e]);
    int d = __ldg(&ei[N_EDGES + e]);
    float4 v = g_pq[(size_t)s * 20 + c];  // p half = f4 slots 0..9
    float* a = ((float*)g_agg2) + (size_t)d * OUT_DIM + c * 4;
    atomicAdd(a + 0, v.x);
    atomicAdd(a + 1, v.y);
    atomicAdd(a + 2, v.z);
    atomicAdd(a + 3, v.w);
}

// ---------------- finalize: out = agg2*inv + b2 + q ----------------
__global__ void k_final(const float4* __restrict__ b24, float4* __restrict__ out4) {
    int idx = blockIdx.x * blockDim.x + threadIdx.x;
    if (idx >= N_NODES * 10) return;
    int row = idx / 10;
    int c = idx % 10;
    float inv = g_inv[row];
    float4 ag = g_agg2[(size_t)row * 10 + c];
    float4 q = g_pq[(size_t)row * 20 + 10 + c];  // q half = f4 slots 10..19
    float4 b = b24[c];
    float4 o;
    o.x = ag.x * inv + b.x + q.x;
    o.y = ag.y * inv + b.y + q.y;
    o.z = ag.z * inv + b.z + q.z;
    o.w = ag.w * inv + b.w + q.w;
    out4[idx] = o;
}

// ---------------- launch ----------------
extern "C" void kernel_launch(void* const* d_in, const int* in_sizes, int n_in,
                              void* d_out, int out_size) {
    const float4* x4 = (const float4*)d_in[0];
    const int* ei = (const int*)d_in[1];   // int32! (JAX x64 disabled)
    const float4* W1l4 = (const float4*)d_in[2];
    const float4* b14 = (const float4*)d_in[3];
    const float4* W1r4 = (const float4*)d_in[4];
    const float4* W2l4 = (const float4*)d_in[5];
    const float4* b24 = (const float4*)d_in[6];
    const float4* W2r4 = (const float4*)d_in[7];
    float4* out4 = (float4*)d_out;

    k_zero<<<(N_NODES * IN_DIM / 4 + 255) / 256, 256>>>();
    k_edge1<<<(N_EDGES * 32 + 255) / 256, 256>>>(x4, ei);
    k_inv<<<(N_NODES + 255) / 256, 256>>>();
    dim3 g1(HID_DIM / 64, (N_NODES + 63) / 64);
    k_gemm1<<<g1, 256>>>(x4, W1l4, W1r4, b14);
    dim3 g2(1, (N_NODES + 63) / 64);
    k_gemm2<<<g2, 320>>>(W2l4, W2r4);
    k_scatter2<<<(N_EDGES * 10 + 255) / 256, 256>>>(ei);
    k_final<<<(N_NODES * 10 + 255) / 256, 256>>>(b24, out4);
}